// round 14
// baseline (speedup 1.0000x reference)
#include <cuda_runtime.h>

#define N_NODES 100000
#define N_EDGES 400000
#define IN_F 128
#define HID 1024
#define OUT_F 64

// Scratch (static device globals — referenced directly by device code only)
__device__ int   g_is64;
__device__ int   g_ei32[2 * N_EDGES];              // normalized edge index
__device__ float g_dinv[N_NODES];
__device__ float g_agg1[(size_t)N_NODES * IN_F];   //  51.2 MB
__device__ float g_h1[(size_t)N_NODES * HID];      // 409.6 MB
__device__ float g_p[(size_t)N_NODES * OUT_F];     //  25.6 MB

template <int TAG>
__device__ __forceinline__ float* buf() {
    if constexpr (TAG == 0) return g_agg1;
    else if constexpr (TAG == 1) return g_h1;
    else return g_p;
}

// ---------------------------------------------------------------------------
// Detect whether edge_index is int64 or int32. If int64 (values < 2^31,
// little-endian), every odd 32-bit word is zero. Sample 512 odd words.
__global__ void k_detect(const int* __restrict__ raw) {
    __shared__ int any_nonzero;
    if (threadIdx.x == 0) any_nonzero = 0;
    __syncthreads();
    int idx = 1 + 2 * (threadIdx.x * (N_EDGES / 512));   // odd words < 2*N_EDGES
    if (raw[idx] != 0) atomicOr(&any_nonzero, 1);
    __syncthreads();
    if (threadIdx.x == 0) g_is64 = any_nonzero ? 0 : 1;
}

// Normalize to int32 [src(0..E-1), dst(E..2E-1)]
__global__ void k_convert(const int* __restrict__ raw) {
    int e = blockIdx.x * blockDim.x + threadIdx.x;
    if (e < 2 * N_EDGES) {
        int is64 = g_is64;
        g_ei32[e] = is64 ? raw[2 * e] : raw[e];
    }
}

// ---------------------------------------------------------------------------
__global__ void k_init_deg() {
    int i = blockIdx.x * blockDim.x + threadIdx.x;
    if (i < N_NODES) g_dinv[i] = 1.0f;   // self-loop weight
}

__global__ void k_deg_edges(const float* __restrict__ ew) {
    int e = blockIdx.x * blockDim.x + threadIdx.x;
    if (e < N_EDGES) {
        int d = g_ei32[N_EDGES + e];
        atomicAdd(&g_dinv[d], ew[e]);
    }
}

__global__ void k_dinv() {
    int i = blockIdx.x * blockDim.x + threadIdx.x;
    if (i < N_NODES) {
        float v = g_dinv[i];
        g_dinv[i] = (v > 0.f) ? rsqrtf(v) : 0.f;
    }
}

// g_agg1[i][f] = x[i][f] * dinv[i]^2        (self-loop term, layer 1)
__global__ void k_selfloop1(const float* __restrict__ x) {
    int idx = blockIdx.x * blockDim.x + threadIdx.x;   // float4 index
    const int total = N_NODES * (IN_F / 4);
    if (idx >= total) return;
    int node = idx / (IN_F / 4);
    float di = g_dinv[node];
    float s  = di * di;
    float4 v = ((const float4*)x)[idx];
    float4 o;
    o.x = v.x * s; o.y = v.y * s; o.z = v.z * s; o.w = v.w * s;
    ((float4*)g_agg1)[idx] = o;
}

// out[i][f] = g_p[i][f] * dinv[i]^2 + b2[f]  (self-loop term + bias, layer 2)
__global__ void k_selfloop2(const float* __restrict__ b2,
                            float* __restrict__ out) {
    int idx = blockIdx.x * blockDim.x + threadIdx.x;
    const int total = N_NODES * (OUT_F / 4);
    if (idx >= total) return;
    int node = idx / (OUT_F / 4);
    int f4   = idx % (OUT_F / 4);
    float di = g_dinv[node];
    float s  = di * di;
    float4 v = ((const float4*)g_p)[idx];
    float4 b = ((const float4*)b2)[f4];
    float4 o;
    o.x = v.x * s + b.x; o.y = v.y * s + b.y;
    o.z = v.z * s + b.z; o.w = v.w * s + b.w;
    ((float4*)out)[idx] = o;
}

// warp-per-edge scatter, layer 1: g_agg1[dst] += norm * x[src]  (128 feats)
__global__ void k_scatter1(const float* __restrict__ ew,
                           const float* __restrict__ x) {
    int warp = (blockIdx.x * blockDim.x + threadIdx.x) >> 5;
    int lane = threadIdx.x & 31;
    if (warp >= N_EDGES) return;
    int s = 0, d = 0;
    float nrm = 0.f;
    if (lane == 0) {
        s = g_ei32[warp];
        d = g_ei32[N_EDGES + warp];
        nrm = g_dinv[s] * ew[warp] * g_dinv[d];
    }
    s   = __shfl_sync(0xffffffffu, s, 0);
    d   = __shfl_sync(0xffffffffu, d, 0);
    nrm = __shfl_sync(0xffffffffu, nrm, 0);

    const float4* xs = (const float4*)(x + (long long)s * IN_F);
    float*        od = g_agg1 + (long long)d * IN_F;
    float4 v = xs[lane];
    atomicAdd(&od[lane * 4 + 0], v.x * nrm);
    atomicAdd(&od[lane * 4 + 1], v.y * nrm);
    atomicAdd(&od[lane * 4 + 2], v.z * nrm);
    atomicAdd(&od[lane * 4 + 3], v.w * nrm);
}

// warp-per-edge scatter, layer 2: out[dst] += norm * g_p[src]  (64 feats)
__global__ void k_scatter2(const float* __restrict__ ew,
                           float* __restrict__ out) {
    int warp = (blockIdx.x * blockDim.x + threadIdx.x) >> 5;
    int lane = threadIdx.x & 31;
    if (warp >= N_EDGES) return;
    int s = 0, d = 0;
    float nrm = 0.f;
    if (lane == 0) {
        s = g_ei32[warp];
        d = g_ei32[N_EDGES + warp];
        nrm = g_dinv[s] * ew[warp] * g_dinv[d];
    }
    s   = __shfl_sync(0xffffffffu, s, 0);
    d   = __shfl_sync(0xffffffffu, d, 0);
    nrm = __shfl_sync(0xffffffffu, nrm, 0);

    const float2* ps = (const float2*)(g_p + (long long)s * OUT_F);
    float*        od = out + (long long)d * OUT_F;
    float2 v = ps[lane];
    atomicAdd(&od[lane * 2 + 0], v.x * nrm);
    atomicAdd(&od[lane * 2 + 1], v.y * nrm);
}

// ---------------------------------------------------------------------------
// fp32 SGEMM with packed f32x2 FFMA (FFMA2): C = A @ B (+bias)(+relu)
// Accumulators packed along M (pairs of adjacent rows); B staged DUPLICATED in
// shared so a 128-bit load yields two replicated (b,b) pairs. Double-buffered
// smem + register prefetch. BM=128 BN=64 BK=16, 256 threads, 8x4 per thread.
template <int M_, int N_, int K_, bool RELU, bool BIAS, int ASEL, int CSEL>
__global__ __launch_bounds__(256)
void sgemm(const float* __restrict__ B, const float* __restrict__ bias) {
    constexpr int BM = 128, BN = 64, BK = 16, TM = 8, TN = 4;
    const float* A = buf<ASEL>();
    float*       C = buf<CSEL>();

    __shared__ float As[2][BK][BM + 4];      // 2*16*132*4 = 16.5 KB
    __shared__ float Bsd[2][BK][2 * BN];     // duplicated: 2*16*128*4 = 16 KB

    const int tid  = threadIdx.x;
    const int brow = blockIdx.y * BM;
    const int bcol = blockIdx.x * BN;
    const int tcol = (tid % 16) * TN;   // 0..60
    const int trow = (tid / 16) * TM;   // 0..120 (multiple of 8)

    // acc2[ip][j]: packed fp32x2 over rows (2*ip, 2*ip+1), column tcol+j
    unsigned long long acc2[TM / 2][TN];
#pragma unroll
    for (int i = 0; i < TM / 2; i++)
#pragma unroll
        for (int j = 0; j < TN; j++) acc2[i][j] = 0ull;

    const int a_r = tid >> 2;           // 0..63
    const int a_c = (tid & 3) * 4;      // 0,4,8,12
    const int b_r = tid >> 4;           // 0..15
    const int b_c = (tid & 15) * 4;     // 0..60

    // ---- prologue: load tile k0=0 into buffer 0
    float4 av[2], bvp;
#pragma unroll
    for (int p = 0; p < 2; p++) {
        int row = brow + a_r + p * 64;
        av[p] = make_float4(0.f, 0.f, 0.f, 0.f);
        if (row < M_)
            av[p] = *(const float4*)(A + (long long)row * K_ + a_c);
    }
    bvp = *(const float4*)(B + (long long)b_r * N_ + bcol + b_c);
#pragma unroll
    for (int p = 0; p < 2; p++) {
        As[0][a_c + 0][a_r + p * 64] = av[p].x;
        As[0][a_c + 1][a_r + p * 64] = av[p].y;
        As[0][a_c + 2][a_r + p * 64] = av[p].z;
        As[0][a_c + 3][a_r + p * 64] = av[p].w;
    }
    *(float4*)&Bsd[0][b_r][2 * b_c]     = make_float4(bvp.x, bvp.x, bvp.y, bvp.y);
    *(float4*)&Bsd[0][b_r][2 * b_c + 4] = make_float4(bvp.z, bvp.z, bvp.w, bvp.w);
    __syncthreads();

    int cur = 0;
    for (int k0 = 0; k0 < K_; k0 += BK) {
        const bool has_next = (k0 + BK < K_);

        // prefetch next tile into registers (overlaps with FFMA2 below)
        if (has_next) {
#pragma unroll
            for (int p = 0; p < 2; p++) {
                int row = brow + a_r + p * 64;
                av[p] = make_float4(0.f, 0.f, 0.f, 0.f);
                if (row < M_)
                    av[p] = *(const float4*)(A + (long long)row * K_ + (k0 + BK) + a_c);
            }
            bvp = *(const float4*)(B + (long long)(k0 + BK + b_r) * N_ + bcol + b_c);
        }

        // compute on current buffer: per kk, 4x LDS.128 + 16x FFMA2
#pragma unroll
        for (int kk = 0; kk < BK; kk++) {
            // a pairs: rows (trow..trow+7) as 4 packed f32x2
            ulonglong2 a01 = *(const ulonglong2*)&As[cur][kk][trow];
            ulonglong2 a23 = *(const ulonglong2*)&As[cur][kk][trow + 4];
            unsigned long long ap[4] = {a01.x, a01.y, a23.x, a23.y};
            // b replicated pairs: (b[j],b[j]) for j = tcol..tcol+3
            ulonglong2 b01 = *(const ulonglong2*)&Bsd[cur][kk][2 * tcol];
            ulonglong2 b23 = *(const ulonglong2*)&Bsd[cur][kk][2 * tcol + 4];
            unsigned long long bp[4] = {b01.x, b01.y, b23.x, b23.y};
#pragma unroll
            for (int i = 0; i < TM / 2; i++)
#pragma unroll
                for (int j = 0; j < TN; j++)
                    asm volatile("fma.rn.f32x2 %0, %1, %2, %0;"
                                 : "+l"(acc2[i][j])
                                 : "l"(ap[i]), "l"(bp[j]));
        }

        // stage prefetched tile into the other buffer
        if (has_next) {
            int nxt = cur ^ 1;
#pragma unroll
            for (int p = 0; p < 2; p++) {
                As[nxt][a_c + 0][a_r + p * 64] = av[p].x;
                As[nxt][a_c + 1][a_r + p * 64] = av[p].y;
                As[nxt][a_c + 2][a_r + p * 64] = av[p].z;
                As[nxt][a_c + 3][a_r + p * 64] = av[p].w;
            }
            *(float4*)&Bsd[nxt][b_r][2 * b_c]     = make_float4(bvp.x, bvp.x, bvp.y, bvp.y);
            *(float4*)&Bsd[nxt][b_r][2 * b_c + 4] = make_float4(bvp.z, bvp.z, bvp.w, bvp.w);
            __syncthreads();
            cur = nxt;
        }
    }

    // epilogue: unpack row pairs, add bias, relu, store
    float4 bv = make_float4(0.f, 0.f, 0.f, 0.f);
    if (BIAS) bv = *(const float4*)(bias + bcol + tcol);
    float bb[TN] = {bv.x, bv.y, bv.z, bv.w};
#pragma unroll
    for (int ip = 0; ip < TM / 2; ip++) {
        float lo[TN], hi[TN];
#pragma unroll
        for (int j = 0; j < TN; j++) {
            unsigned int l, h;
            asm("mov.b64 {%0, %1}, %2;" : "=r"(l), "=r"(h) : "l"(acc2[ip][j]));
            lo[j] = __uint_as_float(l) + bb[j];
            hi[j] = __uint_as_float(h) + bb[j];
            if (RELU) { lo[j] = fmaxf(lo[j], 0.f); hi[j] = fmaxf(hi[j], 0.f); }
        }
        int row0 = brow + trow + 2 * ip;
        if (row0 < M_)
            *(float4*)(C + (long long)row0 * N_ + bcol + tcol) =
                make_float4(lo[0], lo[1], lo[2], lo[3]);
        if (row0 + 1 < M_)
            *(float4*)(C + (long long)(row0 + 1) * N_ + bcol + tcol) =
                make_float4(hi[0], hi[1], hi[2], hi[3]);
    }
}

// ---------------------------------------------------------------------------
extern "C" void kernel_launch(void* const* d_in, const int* in_sizes, int n_in,
                              void* d_out, int out_size) {
    const float* x  = (const float*)d_in[0];
    const int*   ei = (const int*)d_in[1];   // dtype resolved at runtime
    const float* ew = (const float*)d_in[2];
    const float* W1 = (const float*)d_in[3];
    const float* b1 = (const float*)d_in[4];
    const float* W2 = (const float*)d_in[5];
    const float* b2 = (const float*)d_in[6];
    float* out = (float*)d_out;

    const int T = 256;

    // 0) normalize edge_index dtype (int64 vs int32) into g_ei32
    k_detect<<<1, 512>>>(ei);
    k_convert<<<(2 * N_EDGES + T - 1) / T, T>>>(ei);

    // 1) degrees (with self-loop) -> dinv
    k_init_deg<<<(N_NODES + T - 1) / T, T>>>();
    k_deg_edges<<<(N_EDGES + T - 1) / T, T>>>(ew);
    k_dinv<<<(N_NODES + T - 1) / T, T>>>();

    // 2) g_agg1 = A_norm @ x   (self-loop init + edge scatter at 128 feats)
    {
        int total4 = N_NODES * (IN_F / 4);
        k_selfloop1<<<(total4 + T - 1) / T, T>>>(x);
        k_scatter1<<<(N_EDGES * 32 + T - 1) / T, T>>>(ew, x);
    }

    // 3) g_h1 = relu(g_agg1 @ W1 + b1)
    {
        dim3 grid(HID / 64, (N_NODES + 127) / 128);
        sgemm<N_NODES, HID, IN_F, true, true, 0, 1><<<grid, 256>>>(W1, b1);
    }

    // 4) g_p = g_h1 @ W2
    {
        dim3 grid(OUT_F / 64, (N_NODES + 127) / 128);
        sgemm<N_NODES, OUT_F, HID, false, false, 1, 2><<<grid, 256>>>(W2, nullptr);
    }

    // 5) out = A_norm @ g_p + b2  (self-loop init w/ bias + edge scatter at 64)
    {
        int total4 = N_NODES * (OUT_F / 4);
        k_selfloop2<<<(total4 + T - 1) / T, T>>>(b2, out);
        k_scatter2<<<(N_EDGES * 32 + T - 1) / T, T>>>(ew, out);
    }
}